// round 2
// baseline (speedup 1.0000x reference)
#include <cuda_runtime.h>

// Problem constants (B=256, S=4096, V=30)
#define NROWS 1048576          // B*S
#define V 30
#define RPB 256                // rows per block
#define NBLK (NROWS / RPB)     // 4096
#define STRIDE 33              // padded smem row stride (conflict-free scalar reads)

__device__ float g_partial[NBLK];

__device__ __forceinline__ float ex2f(float x) {
    float r; asm("ex2.approx.f32 %0, %1;" : "=f"(r) : "f"(x)); return r;
}
__device__ __forceinline__ float lg2f(float x) {
    float r; asm("lg2.approx.f32 %0, %1;" : "=f"(r) : "f"(x)); return r;
}

__global__ __launch_bounds__(RPB) void mlm_kernel(const float* __restrict__ mlm,
                                                  const int* __restrict__ targets,
                                                  float* __restrict__ out)
{
    __shared__ float tile[RPB * STRIDE];
    __shared__ float wsum[RPB / 32];
    const int tid = threadIdx.x;
    const long long rowbase = (long long)blockIdx.x * RPB;

    // ---- Stage tile: coalesced float2 global loads -> padded smem ----
    // 256 rows * 30 f32 = 7680 floats = 3840 float2; 15 per thread.
    // A float2 never straddles a row boundary (30 is even, elements 2j,2j+1).
    const float2* __restrict__ src =
        (const float2*)mlm + (long long)blockIdx.x * (RPB * V / 2);
#pragma unroll
    for (int k = 0; k < (RPB * V / 2) / RPB; k++) {   // 15 iterations
        int j = tid + k * RPB;
        float2 v = src[j];
        int e = 2 * j;
        int r = e / V;
        int c = e - r * V;
        tile[r * STRIDE + c]     = v.x;
        tile[r * STRIDE + c + 1] = v.y;
    }
    __syncthreads();

    // ---- One thread per row: max, argmax (first occurrence), logsumexp ----
    const float* rowp = tile + tid * STRIDE;
    float m = rowp[0];
#pragma unroll
    for (int i = 1; i < V; i++) m = fmaxf(m, rowp[i]);

    const float L = 1.4426950408889634f;   // log2(e)
    const float mL = m * L;
    float a0 = 0.f, a1 = 0.f, a2 = 0.f, a3 = 0.f;
    int idx = 0;
#pragma unroll
    for (int i = V - 1; i >= 0; i--) {     // descending: last write = smallest i
        float v = rowp[i];
        float e = ex2f(fmaf(v, L, -mL));
        if ((i & 3) == 0) a0 += e;
        else if ((i & 3) == 1) a1 += e;
        else if ((i & 3) == 2) a2 += e;
        else a3 += e;
        if (v == m) idx = i;
    }
    float sumexp = (a0 + a1) + (a2 + a3);

    int t = targets[rowbase + tid];
    float xt = rowp[t];
    // logsumexp = m + ln(sumexp);  nll = logsumexp - x[target]
    float nll = 0.6931471805599453f * lg2f(sumexp) + m - xt;
    float val = (t != 0) ? nll : 0.0f;     // PAD_INDEX = 0 masked out

    out[rowbase + tid] = (float)idx;       // mlm_predictions

    // ---- Deterministic block reduction of masked nll ----
#pragma unroll
    for (int o = 16; o; o >>= 1) val += __shfl_down_sync(0xffffffffu, val, o);
    if ((tid & 31) == 0) wsum[tid >> 5] = val;
    __syncthreads();
    if (tid == 0) {
        float s = 0.f;
#pragma unroll
        for (int w = 0; w < RPB / 32; w++) s += wsum[w];
        g_partial[blockIdx.x] = s;
    }
}

__global__ __launch_bounds__(1024) void finalize_kernel(const float* __restrict__ nsp,
                                                        float* __restrict__ out)
{
    __shared__ double sh[1024];
    int tid = threadIdx.x;
    double s = 0.0;
    for (int i = tid; i < NBLK; i += 1024) s += (double)g_partial[i];
    sh[tid] = s;
    __syncthreads();
    for (int o = 512; o > 0; o >>= 1) {
        if (tid < o) sh[tid] += sh[tid + o];
        __syncthreads();
    }
    if (tid < 256) {
        // nsp argmax over 2: first occurrence on tie -> strict >
        float a = nsp[2 * tid];
        float b = nsp[2 * tid + 1];
        out[NROWS + tid] = (b > a) ? 1.0f : 0.0f;
    }
    if (tid == 0) {
        out[NROWS + 256] = (float)(sh[0] / (double)NROWS);  // mean over all N (incl. pads)
    }
}

extern "C" void kernel_launch(void* const* d_in, const int* in_sizes, int n_in,
                              void* d_out, int out_size)
{
    // metadata order: mlm_outputs, nsp_outputs, mutation_matrix, mlm_targets, is_nexts
    const float* mlm     = (const float*)d_in[0];
    const float* nsp     = (const float*)d_in[1];
    const int*   targets = (const int*)d_in[3];
    float* out = (float*)d_out;

    mlm_kernel<<<NBLK, RPB>>>(mlm, targets, out);
    finalize_kernel<<<1, 1024>>>(nsp, out);
}

// round 4
// speedup vs baseline: 1.3428x; 1.3428x over previous
#include <cuda_runtime.h>

// Problem constants (B=256, S=4096, V=30)
#define NROWS 1048576          // B*S
#define V 30
#define RPB 256                // rows per block
#define NBLK (NROWS / RPB)     // 4096
#define STRIDE 33              // padded smem row stride (conflict-free scalar reads)

__device__ float          g_partial[NBLK];
__device__ unsigned int   g_ticket = 0;

__device__ __forceinline__ float ex2f(float x) {
    float r; asm("ex2.approx.f32 %0, %1;" : "=f"(r) : "f"(x)); return r;
}
__device__ __forceinline__ float lg2f(float x) {
    float r; asm("lg2.approx.f32 %0, %1;" : "=f"(r) : "f"(x)); return r;
}

// Scatter one float4 (global elements e..e+3, e ≡ 0 mod 4 so column c is even)
// into the padded smem tile. Only wrap case is c == 28 (2 elems spill to next row).
__device__ __forceinline__ void scat4(float* __restrict__ tile, int e, float4 v) {
    int r = e / V;
    int c = e - r * V;
    float* p = tile + r * STRIDE + c;
    if (c <= V - 4) {
        p[0] = v.x; p[1] = v.y; p[2] = v.z; p[3] = v.w;
    } else {                        // c == 28: spill z,w to next row cols 0,1
        p[0] = v.x; p[1] = v.y;
        p[STRIDE - (V - 2) + 0] = v.z;   // (r+1)*STRIDE + 0
        p[STRIDE - (V - 2) + 1] = v.w;   // (r+1)*STRIDE + 1
    }
}

__global__ __launch_bounds__(RPB) void mlm_kernel(const float* __restrict__ mlm,
                                                  const int* __restrict__ targets,
                                                  const float* __restrict__ nsp,
                                                  float* __restrict__ out)
{
    __shared__ float tile[RPB * STRIDE];
    __shared__ float wsum[RPB / 32];
    __shared__ bool  is_last;
    const int tid = threadIdx.x;
    const long long rowbase = (long long)blockIdx.x * RPB;

    // ---- Stage tile: coalesced float4 global loads -> padded smem ----
    // 256 rows * 30 f32 = 7680 floats = 1920 float4; 7.5 per thread.
    const float4* __restrict__ src =
        (const float4*)mlm + (long long)blockIdx.x * (RPB * V / 4);
#pragma unroll
    for (int k = 0; k < 7; k++) {
        int j = tid + k * RPB;
        float4 v = src[j];
        scat4(tile, 4 * j, v);
    }
    if (tid < RPB / 2) {                         // tail: 128 remaining float4
        int j = 7 * RPB + tid;
        float4 v = src[j];
        scat4(tile, 4 * j, v);
    }
    __syncthreads();

    // ---- One thread per row: max, argmax (first occurrence), logsumexp ----
    const float* rowp = tile + tid * STRIDE;
    float m = rowp[0];
#pragma unroll
    for (int i = 1; i < V; i++) m = fmaxf(m, rowp[i]);

    const float L = 1.4426950408889634f;   // log2(e)
    const float mL = m * L;
    float a0 = 0.f, a1 = 0.f, a2 = 0.f, a3 = 0.f;
    int idx = 0;
#pragma unroll
    for (int i = V - 1; i >= 0; i--) {     // descending: last write = smallest i
        float v = rowp[i];
        float e = ex2f(fmaf(v, L, -mL));
        if ((i & 3) == 0) a0 += e;
        else if ((i & 3) == 1) a1 += e;
        else if ((i & 3) == 2) a2 += e;
        else a3 += e;
        if (v == m) idx = i;
    }
    float sumexp = (a0 + a1) + (a2 + a3);

    int t = targets[rowbase + tid];
    float xt = rowp[t];
    float nll = 0.6931471805599453f * lg2f(sumexp) + m - xt;
    float val = (t != 0) ? nll : 0.0f;     // PAD_INDEX = 0 masked out

    out[rowbase + tid] = (float)idx;       // mlm_predictions

    // ---- Deterministic block reduction of masked nll ----
#pragma unroll
    for (int o = 16; o; o >>= 1) val += __shfl_down_sync(0xffffffffu, val, o);
    if ((tid & 31) == 0) wsum[tid >> 5] = val;
    __syncthreads();
    if (tid == 0) {
        float s = 0.f;
#pragma unroll
        for (int w = 0; w < RPB / 32; w++) s += wsum[w];
        g_partial[blockIdx.x] = s;
        __threadfence();                                   // publish partial
        unsigned int old = atomicAdd(&g_ticket, 1u);
        is_last = (old == NBLK - 1);
    }
    __syncthreads();

    // ---- Last arriving block: final reduce + nsp argmax + loss ----
    if (is_last) {
        __threadfence();                  // acquire all published partials
        // Each thread sums a fixed strided slice in double -> deterministic.
        double s = 0.0;
#pragma unroll
        for (int k = 0; k < NBLK / RPB; k++)             // 16 per thread
            s += (double)g_partial[tid + k * RPB];
        // deterministic tree reduce via smem doubles
        __shared__ double dsh[RPB];
        dsh[tid] = s;
        __syncthreads();
        for (int o = RPB / 2; o > 0; o >>= 1) {
            if (tid < o) dsh[tid] += dsh[tid + o];
            __syncthreads();
        }
        // nsp argmax over 2 classes (first occurrence on tie -> strict >)
        float a = nsp[2 * tid];
        float b = nsp[2 * tid + 1];
        out[NROWS + tid] = (b > a) ? 1.0f : 0.0f;

        if (tid == 0) {
            out[NROWS + 256] = (float)(dsh[0] / (double)NROWS);
            g_ticket = 0;                 // reset for next graph replay
        }
    }
}

extern "C" void kernel_launch(void* const* d_in, const int* in_sizes, int n_in,
                              void* d_out, int out_size)
{
    // metadata order: mlm_outputs, nsp_outputs, mutation_matrix, mlm_targets, is_nexts
    const float* mlm     = (const float*)d_in[0];
    const float* nsp     = (const float*)d_in[1];
    const int*   targets = (const int*)d_in[3];
    float* out = (float*)d_out;

    mlm_kernel<<<NBLK, RPB>>>(mlm, targets, nsp, out);
}